// round 5
// baseline (speedup 1.0000x reference)
#include <cuda_runtime.h>
#include <cstdint>

// Problem constants
#define T_LEN   128
#define BATCH   8
#define NHEAD   8
#define HD      64
#define DMODEL  512
#define SCALING 0.125f   // 64^-0.5

// Intermediates as device globals (no allocation allowed)
__device__ float g_q[64 * 128 * 64];     // [BH][T][hd], already scaled by SCALING
__device__ float g_k[64 * 128 * 64];
__device__ float g_v[64 * 128 * 64];
__device__ float g_attn[1024 * 512];     // [T*B][512] rows = t*8+b

// ---- packed f32x2 helpers (Blackwell 2x FP32 path) ----
__device__ __forceinline__ unsigned long long pk2(float lo, float hi) {
    unsigned long long r;
    asm("mov.b64 %0, {%1, %2};" : "=l"(r)
        : "r"(__float_as_uint(lo)), "r"(__float_as_uint(hi)));
    return r;
}
__device__ __forceinline__ unsigned long long ffma2(unsigned long long a,
                                                    unsigned long long b,
                                                    unsigned long long c) {
    unsigned long long d;
    asm("fma.rn.f32x2 %0, %1, %2, %3;" : "=l"(d) : "l"(a), "l"(b), "l"(c));
    return d;
}
__device__ __forceinline__ void upk2(unsigned long long v, float& lo, float& hi) {
    unsigned int a, b;
    asm("mov.b64 {%0, %1}, %2;" : "=r"(a), "=r"(b) : "l"(v));
    lo = __uint_as_float(a); hi = __uint_as_float(b);
}

// ============================================================================
// Kernel 1: packed in-projection. grid (8 colblk, 16 rowblk, 3 matrices)
// X [1024 rows=(t*8+b)][512] @ W[z*512+j][:]^T + bias -> scatter to g_{q,k,v}
// ============================================================================
__global__ __launch_bounds__(256)
void proj_kernel(const float* __restrict__ Xq, const float* __restrict__ Xk,
                 const float* __restrict__ Xv, const float* __restrict__ W,
                 const float* __restrict__ Pb)
{
    const int z = blockIdx.z;
    const float* X = (z == 0) ? Xq : (z == 1) ? Xk : Xv;
    float* dst = (z == 0) ? g_q : (z == 1) ? g_k : g_v;
    const int zbase = z << 9;

    __shared__ __align__(16) float Asm[64][36];
    __shared__ __align__(16) float Bsm[32][68];

    const int tid = threadIdx.x;
    const int tx = tid & 15, ty = tid >> 4;
    const int r0 = blockIdx.y << 6, j0 = blockIdx.x << 6;

    unsigned long long acc[4][2];
#pragma unroll
    for (int m = 0; m < 4; m++) { acc[m][0] = 0ull; acc[m][1] = 0ull; }

    const int lr = tid >> 2;         // 0..63
    const int lk = (tid & 3) << 3;   // 0,8,16,24

    for (int kk = 0; kk < 512; kk += 32) {
        float4 a0 = *(const float4*)(X + ((r0 + lr) << 9) + kk + lk);
        float4 a1 = *(const float4*)(X + ((r0 + lr) << 9) + kk + lk + 4);
        *(float4*)&Asm[lr][lk]     = a0;
        *(float4*)&Asm[lr][lk + 4] = a1;
        float4 w0 = *(const float4*)(W + ((zbase + j0 + lr) << 9) + kk + lk);
        float4 w1 = *(const float4*)(W + ((zbase + j0 + lr) << 9) + kk + lk + 4);
        Bsm[lk + 0][lr] = w0.x; Bsm[lk + 1][lr] = w0.y;
        Bsm[lk + 2][lr] = w0.z; Bsm[lk + 3][lr] = w0.w;
        Bsm[lk + 4][lr] = w1.x; Bsm[lk + 5][lr] = w1.y;
        Bsm[lk + 6][lr] = w1.z; Bsm[lk + 7][lr] = w1.w;
        __syncthreads();
#pragma unroll
        for (int k = 0; k < 32; k++) {
            ulonglong2 bp = *(const ulonglong2*)&Bsm[k][tx << 2];
#pragma unroll
            for (int m = 0; m < 4; m++) {
                float av = Asm[(ty << 2) + m][k];
                unsigned long long ad = pk2(av, av);
                acc[m][0] = ffma2(ad, bp.x, acc[m][0]);
                acc[m][1] = ffma2(ad, bp.y, acc[m][1]);
            }
        }
        __syncthreads();
    }

#pragma unroll
    for (int m = 0; m < 4; m++) {
        int rg = r0 + (ty << 2) + m;
        int t = rg >> 3, b = rg & 7;
#pragma unroll
        for (int p = 0; p < 2; p++) {
            float lo, hi; upk2(acc[m][p], lo, hi);
            int jg = j0 + (tx << 2) + (p << 1);
            lo += Pb[zbase + jg]; hi += Pb[zbase + jg + 1];
            if (z == 0) { lo *= SCALING; hi *= SCALING; }
            int hh = jg >> 6, dd = jg & 63;
            int idx = (((b << 3) + hh) << 13) + (t << 6) + dd;
            dst[idx] = lo; dst[idx + 1] = hi;
        }
    }
}

// ============================================================================
// Kernel 2: main trilinear attention. One CTA per (a, batch), loop 8 heads.
// Per head: scores[b,c] = sum_t (q_vec[t]*k[b,t]) * v[c,t]   (128x128x64)
// fused[b] = mean_c(scores+bias) + max_c(scores+bias); softmax over b;
// attn[d] = sum_b w[b]*q[b,d].
// Thread map: 16x16, thread owns b = ty+16m (m<8), c = tx+16n (n<8).
// Pairs of c-slots packed into f32x2 accumulators.
// ============================================================================
__global__ __launch_bounds__(256)
void attn_kernel(const float* __restrict__ bias)
{
    __shared__ __align__(16) float qk_s[128 * 36];
    __shared__ __align__(16) float v_s[128 * 36];
    __shared__ float qvec[64];
    __shared__ float fsm[128];
    __shared__ float wsm[128];
    __shared__ float red[8];
    __shared__ float red2[8];
    __shared__ float part[256];

    const int tid = threadIdx.x;
    const int tx = tid & 15, ty = tid >> 4;
    const int a = blockIdx.x, batch = blockIdx.y;
    const int lane = tid & 31, warp = tid >> 5;

    const float* bbase = bias + (((batch << 7) + a) << 14);  // [b][c] tile base

    for (int h = 0; h < NHEAD; h++) {
        const int i = (batch << 3) + h;
        __syncthreads();
        if (tid < 64) qvec[tid] = g_q[((i << 7) + a) * 64 + tid];

        unsigned long long acc[8][4];
#pragma unroll
        for (int m = 0; m < 8; m++)
#pragma unroll
            for (int p = 0; p < 4; p++) acc[m][p] = 0ull;

        for (int phase = 0; phase < 2; phase++) {
            const int tb = phase << 5;
            __syncthreads();
            // load [128 rows][32 t] tiles; qk pre-multiplied by q_vec
            for (int idx = tid; idx < 1024; idx += 256) {
                int r = idx >> 3;
                int t4 = (idx & 7) << 2;
                const float* kp = g_k + ((i << 7) + r) * 64 + tb + t4;
                const float* vp = g_v + ((i << 7) + r) * 64 + tb + t4;
                float4 kv = *(const float4*)kp;
                float4 vv = *(const float4*)vp;
                float4 qq;
                qq.x = kv.x * qvec[tb + t4 + 0];
                qq.y = kv.y * qvec[tb + t4 + 1];
                qq.z = kv.z * qvec[tb + t4 + 2];
                qq.w = kv.w * qvec[tb + t4 + 3];
                *(float4*)&qk_s[r * 36 + t4] = qq;
                *(float4*)&v_s[r * 36 + t4]  = vv;
            }
            __syncthreads();

#pragma unroll
            for (int t4 = 0; t4 < 32; t4 += 4) {
                float4 qr[8], vr[8];
#pragma unroll
                for (int m = 0; m < 8; m++) {
                    qr[m] = *(const float4*)&qk_s[(ty + (m << 4)) * 36 + t4];
                    vr[m] = *(const float4*)&v_s[(tx + (m << 4)) * 36 + t4];
                }
#pragma unroll
                for (int j = 0; j < 4; j++) {
                    unsigned long long vp2[4];
#pragma unroll
                    for (int p = 0; p < 4; p++)
                        vp2[p] = pk2(((const float*)&vr[2 * p])[j],
                                     ((const float*)&vr[2 * p + 1])[j]);
#pragma unroll
                    for (int m = 0; m < 8; m++) {
                        float qv = ((const float*)&qr[m])[j];
                        unsigned long long qd = pk2(qv, qv);
                        acc[m][0] = ffma2(qd, vp2[0], acc[m][0]);
                        acc[m][1] = ffma2(qd, vp2[1], acc[m][1]);
                        acc[m][2] = ffma2(qd, vp2[2], acc[m][2]);
                        acc[m][3] = ffma2(qd, vp2[3], acc[m][3]);
                    }
                }
            }
        }

        // ---- epilogue: bias add, per-b mean+max over c ----
#pragma unroll
        for (int m = 0; m < 8; m++) {
            int b = ty + (m << 4);
            const float* brow = bbase + (b << 7);
            float ps = 0.f, pm = -3.4e38f;
#pragma unroll
            for (int p = 0; p < 4; p++) {
                float lo, hi; upk2(acc[m][p], lo, hi);
                lo += brow[tx + (p << 5)];
                hi += brow[tx + (p << 5) + 16];
                ps += lo + hi;
                pm = fmaxf(pm, fmaxf(lo, hi));
            }
#pragma unroll
            for (int o = 8; o >= 1; o >>= 1) {
                ps += __shfl_xor_sync(0xffffffffu, ps, o);
                pm = fmaxf(pm, __shfl_xor_sync(0xffffffffu, pm, o));
            }
            if (tx == 0) fsm[b] = ps * (1.f / 128.f) + pm;
        }
        __syncthreads();

        // ---- softmax over b (128) ----
        float f = (tid < 128) ? fsm[tid] : -3.4e38f;
        float mx = f;
#pragma unroll
        for (int o = 16; o >= 1; o >>= 1)
            mx = fmaxf(mx, __shfl_xor_sync(0xffffffffu, mx, o));
        if (lane == 0) red[warp] = mx;
        __syncthreads();
        float M = red[0];
#pragma unroll
        for (int w2 = 1; w2 < 8; w2++) M = fmaxf(M, red[w2]);
        float e = (tid < 128) ? __expf(f - M) : 0.f;
        float sm = e;
#pragma unroll
        for (int o = 16; o >= 1; o >>= 1)
            sm += __shfl_xor_sync(0xffffffffu, sm, o);
        if (lane == 0) red2[warp] = sm;
        __syncthreads();
        float S = red2[0] + red2[1] + red2[2] + red2[3] +
                  red2[4] + red2[5] + red2[6] + red2[7];
        if (tid < 128) wsm[tid] = e / S;
        __syncthreads();

        // ---- attn[d] = sum_b w[b] * q[i][b][d] ----
        const int d = tid & 63, grp = tid >> 6;
        const float* qp = g_q + ((i << 7) + (grp << 5)) * 64 + d;
        float av = 0.f;
#pragma unroll
        for (int b2 = 0; b2 < 32; b2++)
            av = fmaf(wsm[(grp << 5) + b2], qp[b2 << 6], av);
        part[tid] = av;
        __syncthreads();
        if (tid < 64) {
            float r4 = part[tid] + part[tid + 64] + part[tid + 128] + part[tid + 192];
            g_attn[(((a << 3) + batch) << 9) + (h << 6) + tid] = r4;
        }
    }
}

// ============================================================================
// Kernel 3: output projection. out[r][j] = g_attn[r][:] . out_w[j][:] + out_b[j]
// ============================================================================
__global__ __launch_bounds__(256)
void outproj_kernel(const float* __restrict__ Wo, const float* __restrict__ Bo,
                    float* __restrict__ out)
{
    __shared__ __align__(16) float Asm[64][36];
    __shared__ __align__(16) float Bsm[32][68];

    const int tid = threadIdx.x;
    const int tx = tid & 15, ty = tid >> 4;
    const int r0 = blockIdx.y << 6, j0 = blockIdx.x << 6;

    unsigned long long acc[4][2];
#pragma unroll
    for (int m = 0; m < 4; m++) { acc[m][0] = 0ull; acc[m][1] = 0ull; }

    const int lr = tid >> 2;
    const int lk = (tid & 3) << 3;

    for (int kk = 0; kk < 512; kk += 32) {
        float4 a0 = *(const float4*)(g_attn + ((r0 + lr) << 9) + kk + lk);
        float4 a1 = *(const float4*)(g_attn + ((r0 + lr) << 9) + kk + lk + 4);
        *(float4*)&Asm[lr][lk]     = a0;
        *(float4*)&Asm[lr][lk + 4] = a1;
        float4 w0 = *(const float4*)(Wo + ((j0 + lr) << 9) + kk + lk);
        float4 w1 = *(const float4*)(Wo + ((j0 + lr) << 9) + kk + lk + 4);
        Bsm[lk + 0][lr] = w0.x; Bsm[lk + 1][lr] = w0.y;
        Bsm[lk + 2][lr] = w0.z; Bsm[lk + 3][lr] = w0.w;
        Bsm[lk + 4][lr] = w1.x; Bsm[lk + 5][lr] = w1.y;
        Bsm[lk + 6][lr] = w1.z; Bsm[lk + 7][lr] = w1.w;
        __syncthreads();
#pragma unroll
        for (int k = 0; k < 32; k++) {
            ulonglong2 bp = *(const ulonglong2*)&Bsm[k][tx << 2];
#pragma unroll
            for (int m = 0; m < 4; m++) {
                float av = Asm[(ty << 2) + m][k];
                unsigned long long ad = pk2(av, av);
                acc[m][0] = ffma2(ad, bp.x, acc[m][0]);
                acc[m][1] = ffma2(ad, bp.y, acc[m][1]);
            }
        }
        __syncthreads();
    }

#pragma unroll
    for (int m = 0; m < 4; m++) {
        int rg = r0 + (ty << 2) + m;
#pragma unroll
        for (int p = 0; p < 2; p++) {
            float lo, hi; upk2(acc[m][p], lo, hi);
            int jg = j0 + (tx << 2) + (p << 1);
            lo += Bo[jg]; hi += Bo[jg + 1];
            out[(rg << 9) + jg]     = lo;
            out[(rg << 9) + jg + 1] = hi;
        }
    }
}

extern "C" void kernel_launch(void* const* d_in, const int* in_sizes, int n_in,
                              void* d_out, int out_size)
{
    (void)in_sizes; (void)n_in; (void)out_size;
    const float* query = (const float*)d_in[0];
    const float* key   = (const float*)d_in[1];
    const float* value = (const float*)d_in[2];
    const float* cbias = (const float*)d_in[3];
    const float* ipw   = (const float*)d_in[4];
    const float* ipb   = (const float*)d_in[5];
    const float* ow    = (const float*)d_in[6];
    const float* ob    = (const float*)d_in[7];
    float* out = (float*)d_out;

    proj_kernel<<<dim3(8, 16, 3), 256>>>(query, key, value, ipw, ipb);
    attn_kernel<<<dim3(128, 8), 256>>>(cbias);
    outproj_kernel<<<dim3(8, 16), 256>>>(ow, ob, out);
}

// round 7
// speedup vs baseline: 1.6408x; 1.6408x over previous
#include <cuda_runtime.h>
#include <cstdint>

// Problem constants
#define T_LEN   128
#define BATCH   8
#define NHEAD   8
#define HD      64
#define DMODEL  512
#define SCALING 0.125f   // 64^-0.5

// Intermediates as device globals (no allocation allowed)
__device__ float g_q[64 * 128 * 64];     // [BH][T][hd], already scaled by SCALING
__device__ float g_k[64 * 128 * 64];
__device__ float g_v[64 * 128 * 64];
__device__ float g_attn[1024 * 512];     // [T*B][512] rows = a*8+batch

// ---- packed f32x2 helpers (projection kernels) ----
__device__ __forceinline__ unsigned long long pk2(float lo, float hi) {
    unsigned long long r;
    asm("mov.b64 %0, {%1, %2};" : "=l"(r)
        : "r"(__float_as_uint(lo)), "r"(__float_as_uint(hi)));
    return r;
}
__device__ __forceinline__ unsigned long long ffma2(unsigned long long a,
                                                    unsigned long long b,
                                                    unsigned long long c) {
    unsigned long long d;
    asm("fma.rn.f32x2 %0, %1, %2, %3;" : "=l"(d) : "l"(a), "l"(b), "l"(c));
    return d;
}
__device__ __forceinline__ void upk2(unsigned long long v, float& lo, float& hi) {
    unsigned int a, b;
    asm("mov.b64 {%0, %1}, %2;" : "=r"(a), "=r"(b) : "l"(v));
    lo = __uint_as_float(a); hi = __uint_as_float(b);
}

// ---- tf32 helpers (plain PTX, supported on base sm_103 target) ----
__device__ __forceinline__ float tf32r(float x) {
    float r;
    asm("cvt.rna.tf32.f32 %0, %1;" : "=f"(r) : "f"(x));
    return r;
}

// m16n8k8 tf32 MMA: D[16x8] += A[16x8] * B[8x8] (A row-major, B col-major)
__device__ __forceinline__ void mma_tf32(float* d, const uint32_t* a,
                                         const uint32_t* b) {
    asm volatile(
        "mma.sync.aligned.m16n8k8.row.col.f32.tf32.tf32.f32 "
        "{%0,%1,%2,%3}, {%4,%5,%6,%7}, {%8,%9}, {%0,%1,%2,%3};"
        : "+f"(d[0]), "+f"(d[1]), "+f"(d[2]), "+f"(d[3])
        : "r"(a[0]), "r"(a[1]), "r"(a[2]), "r"(a[3]),
          "r"(b[0]), "r"(b[1]));
}

// ============================================================================
// Kernel 1: packed in-projection (unchanged, passing)
// ============================================================================
__global__ __launch_bounds__(256)
void proj_kernel(const float* __restrict__ Xq, const float* __restrict__ Xk,
                 const float* __restrict__ Xv, const float* __restrict__ W,
                 const float* __restrict__ Pb)
{
    const int z = blockIdx.z;
    const float* X = (z == 0) ? Xq : (z == 1) ? Xk : Xv;
    float* dst = (z == 0) ? g_q : (z == 1) ? g_k : g_v;
    const int zbase = z << 9;

    __shared__ __align__(16) float Asm[64][36];
    __shared__ __align__(16) float Bsm[32][68];

    const int tid = threadIdx.x;
    const int tx = tid & 15, ty = tid >> 4;
    const int r0 = blockIdx.y << 6, j0 = blockIdx.x << 6;

    unsigned long long acc[4][2];
#pragma unroll
    for (int m = 0; m < 4; m++) { acc[m][0] = 0ull; acc[m][1] = 0ull; }

    const int lr = tid >> 2;
    const int lk = (tid & 3) << 3;

    for (int kk = 0; kk < 512; kk += 32) {
        float4 a0 = *(const float4*)(X + ((r0 + lr) << 9) + kk + lk);
        float4 a1 = *(const float4*)(X + ((r0 + lr) << 9) + kk + lk + 4);
        *(float4*)&Asm[lr][lk]     = a0;
        *(float4*)&Asm[lr][lk + 4] = a1;
        float4 w0 = *(const float4*)(W + ((zbase + j0 + lr) << 9) + kk + lk);
        float4 w1 = *(const float4*)(W + ((zbase + j0 + lr) << 9) + kk + lk + 4);
        Bsm[lk + 0][lr] = w0.x; Bsm[lk + 1][lr] = w0.y;
        Bsm[lk + 2][lr] = w0.z; Bsm[lk + 3][lr] = w0.w;
        Bsm[lk + 4][lr] = w1.x; Bsm[lk + 5][lr] = w1.y;
        Bsm[lk + 6][lr] = w1.z; Bsm[lk + 7][lr] = w1.w;
        __syncthreads();
#pragma unroll
        for (int k = 0; k < 32; k++) {
            ulonglong2 bp = *(const ulonglong2*)&Bsm[k][tx << 2];
#pragma unroll
            for (int m = 0; m < 4; m++) {
                float av = Asm[(ty << 2) + m][k];
                unsigned long long ad = pk2(av, av);
                acc[m][0] = ffma2(ad, bp.x, acc[m][0]);
                acc[m][1] = ffma2(ad, bp.y, acc[m][1]);
            }
        }
        __syncthreads();
    }

#pragma unroll
    for (int m = 0; m < 4; m++) {
        int rg = r0 + (ty << 2) + m;
        int t = rg >> 3, b = rg & 7;
#pragma unroll
        for (int p = 0; p < 2; p++) {
            float lo, hi; upk2(acc[m][p], lo, hi);
            int jg = j0 + (tx << 2) + (p << 1);
            lo += Pb[zbase + jg]; hi += Pb[zbase + jg + 1];
            if (z == 0) { lo *= SCALING; hi *= SCALING; }
            int hh = jg >> 6, dd = jg & 63;
            int idx = (((b << 3) + hh) << 13) + (t << 6) + dd;
            dst[idx] = lo; dst[idx + 1] = hi;
        }
    }
}

// ============================================================================
// Kernel 2: trilinear attention via mma.sync tf32 (tensor pipe, base target).
// One CTA per (a, batch); loop 8 heads. Per head:
//   scores[b,c] = sum_t (q[a,t]*k[b,t]) * v[c,t]  =  QK[128x64] @ V[128x64]^T
// Warp tile: 32(b) x 64(c); 2 m-tiles x 8 n-tiles; K in 2 phases of 32.
// Epilogue fuses bias + mean/max over c; softmax over b; attn = w . q.
// ============================================================================
__global__ __launch_bounds__(256)
void attn_kernel(const float* __restrict__ bias)
{
    __shared__ __align__(16) float qk_s[128 * 36];   // [b][k-phase 32]
    __shared__ __align__(16) float v_s[128 * 36];    // [c][k-phase 32]
    __shared__ float qvec[64];
    __shared__ float psum[128], pmax[128];
    __shared__ float fsm[128], wsm[128];
    __shared__ float red[8], red2[8];
    __shared__ float part[256];

    const int tid = threadIdx.x;
    const int warp = tid >> 5, lane = tid & 31;
    const int g = lane >> 2;       // 0..7  (fragment row group)
    const int q4 = lane & 3;       // 0..3  (fragment col group)
    const int a = blockIdx.x, batch = blockIdx.y;

    const int wb = (warp & 3) << 5;   // b-row base: 0,32,64,96
    const int wc = (warp >> 2) << 6;  // c-col base: 0 or 64

    const float* bbase = bias + (((batch << 7) + a) << 14);

    for (int h = 0; h < NHEAD; h++) {
        const int i = (batch << 3) + h;
        __syncthreads();
        if (tid < 64) qvec[tid] = g_q[(((i << 7) + a) << 6) + tid];

        float acc[2][8][4];
#pragma unroll
        for (int m = 0; m < 2; m++)
#pragma unroll
            for (int n = 0; n < 8; n++)
#pragma unroll
                for (int r = 0; r < 4; r++) acc[m][n][r] = 0.f;

        for (int phase = 0; phase < 2; phase++) {
            const int tb = phase << 5;
            __syncthreads();
            // stage qk (tf32(k*q)) and v (tf32) tiles: [128 rows][32 k]
            for (int idx = tid; idx < 1024; idx += 256) {
                int r = idx >> 3;
                int t4 = (idx & 7) << 2;
                const float4 kv = *(const float4*)
                    (g_k + (((i << 7) + r) << 6) + tb + t4);
                const float4 vv = *(const float4*)
                    (g_v + (((i << 7) + r) << 6) + tb + t4);
                float4 qq;
                qq.x = tf32r(kv.x * qvec[tb + t4 + 0]);
                qq.y = tf32r(kv.y * qvec[tb + t4 + 1]);
                qq.z = tf32r(kv.z * qvec[tb + t4 + 2]);
                qq.w = tf32r(kv.w * qvec[tb + t4 + 3]);
                float4 vt;
                vt.x = tf32r(vv.x); vt.y = tf32r(vv.y);
                vt.z = tf32r(vv.z); vt.w = tf32r(vv.w);
                *(float4*)&qk_s[r * 36 + t4] = qq;
                *(float4*)&v_s[r * 36 + t4]  = vt;
            }
            __syncthreads();

#pragma unroll
            for (int ks = 0; ks < 4; ks++) {
                const int k0 = ks << 3;
                uint32_t bf[8][2];
#pragma unroll
                for (int n = 0; n < 8; n++) {
                    const int c = wc + (n << 3) + g;
                    bf[n][0] = __float_as_uint(v_s[c * 36 + k0 + q4]);
                    bf[n][1] = __float_as_uint(v_s[c * 36 + k0 + q4 + 4]);
                }
#pragma unroll
                for (int m = 0; m < 2; m++) {
                    const int r0 = wb + (m << 4) + g;
                    uint32_t af[4];
                    af[0] = __float_as_uint(qk_s[r0 * 36 + k0 + q4]);
                    af[1] = __float_as_uint(qk_s[(r0 + 8) * 36 + k0 + q4]);
                    af[2] = __float_as_uint(qk_s[r0 * 36 + k0 + q4 + 4]);
                    af[3] = __float_as_uint(qk_s[(r0 + 8) * 36 + k0 + q4 + 4]);
#pragma unroll
                    for (int n = 0; n < 8; n++)
                        mma_tf32(acc[m][n], af, bf[n]);
                }
            }
        }

        // ---- epilogue: bias add + per-row sum/max over this warp's 64 c ----
        // D layout: regs (0,1) -> row r0+g, cols q4*2, q4*2+1
        //           regs (2,3) -> row r0+g+8, same cols
        float sv[4], mv[4];
        int rw[4];
#pragma unroll
        for (int m = 0; m < 2; m++) {
#pragma unroll
            for (int rh = 0; rh < 2; rh++) {
                const int row = wb + (m << 4) + (rh << 3) + g;
                const float2* br = (const float2*)
                    (bbase + (row << 7) + wc) + q4;
                float s = 0.f, mx = -3.4e38f;
#pragma unroll
                for (int n = 0; n < 8; n++) {
                    float2 bb = br[n << 2];
                    float d0 = acc[m][n][(rh << 1) + 0] + bb.x;
                    float d1 = acc[m][n][(rh << 1) + 1] + bb.y;
                    s += d0 + d1;
                    mx = fmaxf(mx, fmaxf(d0, d1));
                }
                s += __shfl_xor_sync(0xffffffffu, s, 1);
                s += __shfl_xor_sync(0xffffffffu, s, 2);
                mx = fmaxf(mx, __shfl_xor_sync(0xffffffffu, mx, 1));
                mx = fmaxf(mx, __shfl_xor_sync(0xffffffffu, mx, 2));
                sv[(m << 1) + rh] = s;
                mv[(m << 1) + rh] = mx;
                rw[(m << 1) + rh] = row;
            }
        }
        if (q4 == 0 && warp < 4) {
#pragma unroll
            for (int e = 0; e < 4; e++) { psum[rw[e]] = sv[e]; pmax[rw[e]] = mv[e]; }
        }
        __syncthreads();
        if (q4 == 0 && warp >= 4) {
#pragma unroll
            for (int e = 0; e < 4; e++)
                fsm[rw[e]] = (sv[e] + psum[rw[e]]) * (1.f / 128.f) +
                             fmaxf(mv[e], pmax[rw[e]]);
        }
        __syncthreads();

        // ---- softmax over b (128) ----
        float f = (tid < 128) ? fsm[tid] : -3.4e38f;
        float mx = f;
#pragma unroll
        for (int o = 16; o >= 1; o >>= 1)
            mx = fmaxf(mx, __shfl_xor_sync(0xffffffffu, mx, o));
        if (lane == 0) red[warp] = mx;
        __syncthreads();
        float M = red[0];
#pragma unroll
        for (int w2 = 1; w2 < 8; w2++) M = fmaxf(M, red[w2]);
        float e = (tid < 128) ? __expf(f - M) : 0.f;
        float sm = e;
#pragma unroll
        for (int o = 16; o >= 1; o >>= 1)
            sm += __shfl_xor_sync(0xffffffffu, sm, o);
        if (lane == 0) red2[warp] = sm;
        __syncthreads();
        float S = red2[0] + red2[1] + red2[2] + red2[3] +
                  red2[4] + red2[5] + red2[6] + red2[7];
        if (tid < 128) wsm[tid] = e / S;
        __syncthreads();

        // ---- attn[d] = sum_b w[b] * q[i][b][d] ----
        const int d = tid & 63, grp = tid >> 6;
        const float* qp = g_q + (((i << 7) + (grp << 5)) << 6) + d;
        float av = 0.f;
#pragma unroll
        for (int b2 = 0; b2 < 32; b2++)
            av = fmaf(wsm[(grp << 5) + b2], qp[b2 << 6], av);
        part[tid] = av;
        __syncthreads();
        if (tid < 64) {
            float r4 = part[tid] + part[tid + 64] + part[tid + 128] + part[tid + 192];
            g_attn[(((a << 3) + batch) << 9) + (h << 6) + tid] = r4;
        }
    }
}

// ============================================================================
// Kernel 3: output projection (unchanged, passing)
// ============================================================================
__global__ __launch_bounds__(256)
void outproj_kernel(const float* __restrict__ Wo, const float* __restrict__ Bo,
                    float* __restrict__ out)
{
    __shared__ __align__(16) float Asm[64][36];
    __shared__ __align__(16) float Bsm[32][68];

    const int tid = threadIdx.x;
    const int tx = tid & 15, ty = tid >> 4;
    const int r0 = blockIdx.y << 6, j0 = blockIdx.x << 6;

    unsigned long long acc[4][2];
#pragma unroll
    for (int m = 0; m < 4; m++) { acc[m][0] = 0ull; acc[m][1] = 0ull; }

    const int lr = tid >> 2;
    const int lk = (tid & 3) << 3;

    for (int kk = 0; kk < 512; kk += 32) {
        float4 a0 = *(const float4*)(g_attn + ((r0 + lr) << 9) + kk + lk);
        float4 a1 = *(const float4*)(g_attn + ((r0 + lr) << 9) + kk + lk + 4);
        *(float4*)&Asm[lr][lk]     = a0;
        *(float4*)&Asm[lr][lk + 4] = a1;
        float4 w0 = *(const float4*)(Wo + ((j0 + lr) << 9) + kk + lk);
        float4 w1 = *(const float4*)(Wo + ((j0 + lr) << 9) + kk + lk + 4);
        Bsm[lk + 0][lr] = w0.x; Bsm[lk + 1][lr] = w0.y;
        Bsm[lk + 2][lr] = w0.z; Bsm[lk + 3][lr] = w0.w;
        Bsm[lk + 4][lr] = w1.x; Bsm[lk + 5][lr] = w1.y;
        Bsm[lk + 6][lr] = w1.z; Bsm[lk + 7][lr] = w1.w;
        __syncthreads();
#pragma unroll
        for (int k = 0; k < 32; k++) {
            ulonglong2 bp = *(const ulonglong2*)&Bsm[k][tx << 2];
#pragma unroll
            for (int m = 0; m < 4; m++) {
                float av = Asm[(ty << 2) + m][k];
                unsigned long long ad = pk2(av, av);
                acc[m][0] = ffma2(ad, bp.x, acc[m][0]);
                acc[m][1] = ffma2(ad, bp.y, acc[m][1]);
            }
        }
        __syncthreads();
    }

#pragma unroll
    for (int m = 0; m < 4; m++) {
        int rg = r0 + (ty << 2) + m;
#pragma unroll
        for (int p = 0; p < 2; p++) {
            float lo, hi; upk2(acc[m][p], lo, hi);
            int jg = j0 + (tx << 2) + (p << 1);
            lo += Bo[jg]; hi += Bo[jg + 1];
            out[(rg << 9) + jg]     = lo;
            out[(rg << 9) + jg + 1] = hi;
        }
    }
}

extern "C" void kernel_launch(void* const* d_in, const int* in_sizes, int n_in,
                              void* d_out, int out_size)
{
    (void)in_sizes; (void)n_in; (void)out_size;
    const float* query = (const float*)d_in[0];
    const float* key   = (const float*)d_in[1];
    const float* value = (const float*)d_in[2];
    const float* cbias = (const float*)d_in[3];
    const float* ipw   = (const float*)d_in[4];
    const float* ipb   = (const float*)d_in[5];
    const float* ow    = (const float*)d_in[6];
    const float* ob    = (const float*)d_in[7];
    float* out = (float*)d_out;

    proj_kernel<<<dim3(8, 16, 3), 256>>>(query, key, value, ipw, ipb);
    attn_kernel<<<dim3(128, 8), 256>>>(cbias);
    outproj_kernel<<<dim3(8, 16), 256>>>(ow, ob, out);
}